// round 11
// baseline (speedup 1.0000x reference)
#include <cuda_runtime.h>
#include <cuda_bf16.h>
#include <cstdint>

// CALayer SE, single-pass, FREE-RUNNING persistent kernel (no lockstep).
// 1024 co-resident blocks (LB(256,7)), each owns a quarter-plane (16KB/batch):
//   round b: [b>=2] check flag(b-2) (2-round-stale -> ~never blocks),
//            scale chunk b-2 (half from smem buf, half ld.cg from L2), st.cs;
//            then read+sum chunk b (half ld.cs -> smem retain, half ld.cg),
//            publish partial; designated block per batch computes the MLP ONCE
//            and sets the flag. Blocks never synchronize chip-wide per round,
//            so DRAM sees mixed read+write streams continuously.

#define BATCH 16
#define CHAN 256
#define CR 16
#define HW 16384                 // floats per plane
#define PLANE_F4 (HW/4)          // 4096
#define QF4 (PLANE_F4/4)         // 1024 float4 per quarter chunk
#define HALF_F4 (QF4/2)          // 512 float4 (8KB) per half
#define NBLK 1024
#define TPB 256

__device__ float g_part[BATCH * CHAN * 4];
__device__ float g_scale[BATCH * CHAN];
__device__ int   g_cnt[BATCH];
__device__ int   g_flag[BATCH];

__global__ void init_kernel() {
    if (threadIdx.x < BATCH) { g_cnt[threadIdx.x] = 0; g_flag[threadIdx.x] = 0; }
}

__device__ __forceinline__ void stcs4(float4* p, float4 v) {
    asm volatile("st.global.cs.v4.f32 [%0], {%1,%2,%3,%4};"
                 :: "l"(p), "f"(v.x), "f"(v.y), "f"(v.z), "f"(v.w) : "memory");
}
__device__ __forceinline__ float4 ldcs4(const float4* p) {
    float4 v;
    asm volatile("ld.global.cs.v4.f32 {%0,%1,%2,%3}, [%4];"
                 : "=f"(v.x), "=f"(v.y), "=f"(v.z), "=f"(v.w) : "l"(p));
    return v;
}
__device__ __forceinline__ float4 ldcg4(const float4* p) {
    float4 v;
    asm volatile("ld.global.cg.v4.f32 {%0,%1,%2,%3}, [%4];"
                 : "=f"(v.x), "=f"(v.y), "=f"(v.z), "=f"(v.w) : "l"(p));
    return v;
}
__device__ __forceinline__ int ld_flag(const int* p) {
    int v;
    asm volatile("ld.global.cg.s32 %0, [%1];" : "=r"(v) : "l"(p));
    return v;
}

__global__ __launch_bounds__(TPB, 7) void fused_se_kernel(
    const float* __restrict__ x, float* __restrict__ out,
    const float* __restrict__ w1, const float* __restrict__ b1,
    const float* __restrict__ w2, const float* __restrict__ b2)
{
    __shared__ float4 buf[2][HALF_F4];   // 16KB: retained first-half chunks
    __shared__ float red[128];           // reduce scratch (512B)
    __shared__ float shid[CR];

    const int chan    = blockIdx.x >> 2;
    const int quarter = blockIdx.x & 3;
    const int tid  = threadIdx.x;
    const int lane = tid & 31;
    const int wid  = tid >> 5;
    const size_t qoff = (size_t)quarter * QF4;

    const float4* __restrict__ x4 = reinterpret_cast<const float4*>(x);
    float4* __restrict__ o4 = reinterpret_cast<float4*>(out);

    auto chunk_ptr = [&](int b) {
        return x4 + (size_t)((b << 8) | chan) * PLANE_F4 + qoff;
    };

    // ---- read + sum chunk b; retain half A in smem buf[b&1]; publish ----
    auto read_publish = [&](int b) {
        const float4* __restrict__ xp = chunk_ptr(b);
        float4 a0 = ldcs4(&xp[tid]);                    // half A -> smem
        float4 a1 = ldcs4(&xp[tid + TPB]);
        float4 b0 = ldcg4(&xp[tid + 2 * TPB]);          // half B -> L2 resident
        float4 b1v = ldcg4(&xp[tid + 3 * TPB]);
        buf[b & 1][tid]       = a0;
        buf[b & 1][tid + TPB] = a1;
        float acc = ((a0.x + a0.y) + (a0.z + a0.w))
                  + ((a1.x + a1.y) + (a1.z + a1.w))
                  + ((b0.x + b0.y) + (b0.z + b0.w))
                  + ((b1v.x + b1v.y) + (b1v.z + b1v.w));
        #pragma unroll
        for (int o = 16; o; o >>= 1) acc += __shfl_xor_sync(0xFFFFFFFF, acc, o);
        if (lane == 0) red[wid] = acc;
        __syncthreads();
        if (tid == 0) {
            float t = 0.f;
            #pragma unroll
            for (int w = 0; w < 8; w++) t += red[w];
            g_part[(((b << 8) | chan) << 2) + quarter] = t;
            __threadfence();
            atomicAdd(&g_cnt[b], 1);
        }
    };

    // ---- designated block: wait all partials of b, compute MLP once ----
    auto mlp_publish = [&](int b) {
        if (tid == 0) {
            while (atomicAdd(&g_cnt[b], 0) < NBLK) __nanosleep(64);
            __threadfence();
        }
        __syncthreads();
        // mean for channel tid
        const int q = ((b << 8) + tid) * 4;
        float m = (__ldcg(&g_part[q]) + __ldcg(&g_part[q + 1]) +
                   __ldcg(&g_part[q + 2]) + __ldcg(&g_part[q + 3])) * (1.0f / HW);
        // 16 hidden-row partial products per thread, block-reduced
        float t[CR];
        #pragma unroll
        for (int r = 0; r < CR; r++) t[r] = __ldg(&w1[r * CHAN + tid]) * m;
        #pragma unroll
        for (int r = 0; r < CR; r++) {
            #pragma unroll
            for (int o = 16; o; o >>= 1) t[r] += __shfl_xor_sync(0xFFFFFFFF, t[r], o);
        }
        if (lane == 0) {
            #pragma unroll
            for (int r = 0; r < CR; r++) red[wid * CR + r] = t[r];
        }
        __syncthreads();
        if (tid < CR) {
            float h = 0.f;
            #pragma unroll
            for (int w = 0; w < 8; w++) h += red[w * CR + tid];
            shid[tid] = fmaxf(h + __ldg(&b1[tid]), 0.f);
        }
        __syncthreads();
        float acc = __ldg(&b2[tid]);
        #pragma unroll
        for (int r = 0; r < CR; r++)
            acc += __ldg(&w2[tid * CR + r]) * shid[r];
        g_scale[(b << 8) + tid] = 1.0f / (1.0f + __expf(-acc));
        __threadfence();
        __syncthreads();
        if (tid == 0) g_flag[b] = 1;
    };

    // ---- scale chunk b: half A from smem, half B from L2; stream out ----
    auto scale_out = [&](int b) {
        if (tid == 0) {
            while (ld_flag(&g_flag[b]) == 0) __nanosleep(64);
            __threadfence();
        }
        __syncthreads();
        const float sc = __ldcg(&g_scale[(b << 8) + chan]);
        const float4* __restrict__ xp = chunk_ptr(b);
        float4* __restrict__ op = o4 + (size_t)((b << 8) | chan) * PLANE_F4 + qoff;
        float4 a0 = buf[b & 1][tid];
        float4 a1 = buf[b & 1][tid + TPB];
        float4 b0 = ldcg4(&xp[tid + 2 * TPB]);   // L2 hit (read 2 rounds ago)
        float4 b1v = ldcg4(&xp[tid + 3 * TPB]);
        a0.x *= sc; a0.y *= sc; a0.z *= sc; a0.w *= sc;
        a1.x *= sc; a1.y *= sc; a1.z *= sc; a1.w *= sc;
        b0.x *= sc; b0.y *= sc; b0.z *= sc; b0.w *= sc;
        b1v.x *= sc; b1v.y *= sc; b1v.z *= sc; b1v.w *= sc;
        stcs4(&op[tid],           a0);
        stcs4(&op[tid + TPB],     a1);
        stcs4(&op[tid + 2 * TPB], b0);
        stcs4(&op[tid + 3 * TPB], b1v);
    };

    // ---------- free-running pipeline, depth 2 ----------
    read_publish(0);
    if (blockIdx.x == 0 * 64) mlp_publish(0);
    read_publish(1);
    if (blockIdx.x == 1 * 64) mlp_publish(1);

    for (int b = 2; b < BATCH; b++) {
        scale_out(b - 2);            // flag 2 rounds stale -> non-blocking
        read_publish(b);             // overwrites buf[b&1] (same-thread slots)
        if (blockIdx.x == b * 64) mlp_publish(b);
    }
    scale_out(BATCH - 2);
    scale_out(BATCH - 1);
}

extern "C" void kernel_launch(void* const* d_in, const int* in_sizes, int n_in,
                              void* d_out, int out_size) {
    const float* x  = (const float*)d_in[0];
    const float* w1 = (const float*)d_in[1];
    const float* b1 = (const float*)d_in[2];
    const float* w2 = (const float*)d_in[3];
    const float* b2 = (const float*)d_in[4];
    float* out = (float*)d_out;

    init_kernel<<<1, 32>>>();
    fused_se_kernel<<<NBLK, TPB>>>(x, out, w1, b1, w2, b2);
}

// round 12
// speedup vs baseline: 1.6817x; 1.6817x over previous
#include <cuda_runtime.h>
#include <cuda_bf16.h>
#include <cstdint>

// CALayer SE, single-pass persistent pipelined kernel (R5 base + prefetch +
// self-resetting counters, single launch).
// 1024 co-resident blocks (LB(256,7): 7x148=1036 slots), each owns a
// quarter-plane (16KB) per batch. Pipeline over 16 batches:
//   round b: read+sum batch b (fills L2), publish counter;
//            prefetch batch b+1 chunk to L2 (keeps DRAM busy through gate);
//            gate(b-1): spin (short), means, tiny MLP;
//            phase C: re-read b-1 chunk (L2 hit), scale, st.cs out.
// Counters self-reset via g_done so no init kernel is needed.
// DRAM traffic: x read once + out written once = 537MB.

#define BATCH 16
#define CHAN 256
#define CR 16
#define HW 16384               // floats per plane
#define PLANE_F4 (HW/4)        // 4096
#define QF4 (PLANE_F4/4)       // 1024 float4 per quarter chunk
#define NBLK 1024
#define TPB 256

__device__ float g_part[BATCH * CHAN * 4];
__device__ int   g_cnt[BATCH];
__device__ int   g_done[BATCH];

__device__ __forceinline__ void stcs4(float4* p, float4 v) {
    asm volatile("st.global.cs.v4.f32 [%0], {%1,%2,%3,%4};"
                 :: "l"(p), "f"(v.x), "f"(v.y), "f"(v.z), "f"(v.w) : "memory");
}
__device__ __forceinline__ void prefetchL2(const void* p) {
    asm volatile("prefetch.global.L2 [%0];" :: "l"(p));
}

__global__ __launch_bounds__(TPB, 7) void fused_se_kernel(
    const float* __restrict__ x, float* __restrict__ out,
    const float* __restrict__ w1, const float* __restrict__ b1,
    const float* __restrict__ w2, const float* __restrict__ b2)
{
    __shared__ float sred[8];
    __shared__ float smean[CHAN];
    __shared__ float shid[CR];
    __shared__ float sscale;

    const int chan    = blockIdx.x >> 2;   // 0..255
    const int quarter = blockIdx.x & 3;    // 0..3
    const int tid  = threadIdx.x;
    const int lane = tid & 31;
    const int wid  = tid >> 5;
    const size_t qoff = (size_t)quarter * QF4;

    const float4* __restrict__ x4 = reinterpret_cast<const float4*>(x);
    float4* __restrict__ o4 = reinterpret_cast<float4*>(out);

    auto read_sum = [&](int b) {
        const int p = (b << 8) | chan;
        const float4* __restrict__ xp = x4 + (size_t)p * PLANE_F4 + qoff;
        float acc = 0.f;
        #pragma unroll
        for (int i = 0; i < 4; i++) {
            float4 v = xp[tid + i * TPB];          // .ca -> L2 resident
            acc += (v.x + v.y) + (v.z + v.w);
        }
        #pragma unroll
        for (int o = 16; o; o >>= 1) acc += __shfl_xor_sync(0xFFFFFFFF, acc, o);
        if (lane == 0) sred[wid] = acc;
        __syncthreads();
        if (tid == 0) {
            float t = 0.f;
            #pragma unroll
            for (int w = 0; w < 8; w++) t += sred[w];
            g_part[(p << 2) + quarter] = t;
            __threadfence();
            atomicAdd(&g_cnt[b], 1);
        }
        __syncthreads();   // sred reusable next round
    };

    // fire-and-forget prefetch of batch b's chunk into L2 (128 lines of 128B)
    auto prefetch_chunk = [&](int b) {
        const char* base = reinterpret_cast<const char*>(
            x4 + (size_t)((b << 8) | chan) * PLANE_F4 + qoff);
        if (tid < 128) prefetchL2(base + tid * 128);
    };

    auto gate_scale = [&](int b) {
        // gate: wait until all 1024 blocks published batch b
        if (tid == 0) {
            while (atomicAdd(&g_cnt[b], 0) < NBLK) __nanosleep(64);
            __threadfence();
            // self-reset: last block through the gate zeroes the counters
            if (atomicAdd(&g_done[b], 1) == NBLK - 1) {
                atomicExch(&g_cnt[b], 0);
                atomicExch(&g_done[b], 0);
            }
        }
        __syncthreads();
        // means (tid == channel index)
        {
            const int q = ((b << 8) + tid) * 4;
            smean[tid] = (__ldcg(&g_part[q]) + __ldcg(&g_part[q + 1]) +
                          __ldcg(&g_part[q + 2]) + __ldcg(&g_part[q + 3])) * (1.0f / HW);
        }
        __syncthreads();
        // hidden layer: 8 warps x 2 rows
        #pragma unroll
        for (int k = 0; k < 2; k++) {
            const int r = wid * 2 + k;
            float acc = 0.f;
            #pragma unroll
            for (int c = lane; c < CHAN; c += 32)
                acc += __ldg(&w1[r * CHAN + c]) * smean[c];
            #pragma unroll
            for (int o = 16; o; o >>= 1) acc += __shfl_xor_sync(0xFFFFFFFF, acc, o);
            if (lane == 0) shid[r] = fmaxf(acc + __ldg(&b1[r]), 0.f);
        }
        __syncthreads();
        if (tid == 0) {
            float acc = __ldg(&b2[chan]);
            #pragma unroll
            for (int r = 0; r < CR; r++)
                acc += __ldg(&w2[chan * CR + r]) * shid[r];
            sscale = 1.0f / (1.0f + __expf(-acc));
        }
        __syncthreads();
        // phase C: re-read from L2, scale, stream out
        const float sc = sscale;
        const int p = (b << 8) | chan;
        const float4* __restrict__ xp = x4 + (size_t)p * PLANE_F4 + qoff;
        float4* __restrict__ op = o4 + (size_t)p * PLANE_F4 + qoff;
        #pragma unroll
        for (int i = 0; i < 4; i++) {
            float4 v = xp[tid + i * TPB];          // L2 hit
            v.x *= sc; v.y *= sc; v.z *= sc; v.w *= sc;
            stcs4(&op[tid + i * TPB], v);
        }
        __syncthreads();
    };

    // ---------- pipelined main loop ----------
    read_sum(0);
    for (int b = 1; b < BATCH; b++) {
        read_sum(b);
        prefetch_chunk(b + 1 < BATCH ? b + 1 : b);  // keep DRAM busy in gate
        gate_scale(b - 1);
    }
    gate_scale(BATCH - 1);
}

extern "C" void kernel_launch(void* const* d_in, const int* in_sizes, int n_in,
                              void* d_out, int out_size) {
    const float* x  = (const float*)d_in[0];
    const float* w1 = (const float*)d_in[1];
    const float* b1 = (const float*)d_in[2];
    const float* w2 = (const float*)d_in[3];
    const float* b2 = (const float*)d_in[4];
    float* out = (float*)d_out;

    fused_se_kernel<<<NBLK, TPB>>>(x, out, w1, b1, w2, b2);
}